// round 7
// baseline (speedup 1.0000x reference)
#include <cuda_runtime.h>
#include <cuda_bf16.h>

// Sparsemax over last dim, rows of N=1024 fp32.
// One WARP per row. Row is NOT held in registers: pass1 streams it from DRAM
// (warp max), passes 2/4 re-read it from L1 (4KB/row stays resident).
// Reloads use asm volatile ld.global.ca so the compiler cannot CSE them back
// into a register-resident row (which would cap occupancy at regs=64).
// tau: candidate compaction over {x > max-1} + exact closed-form rank test.

static constexpr int N = 1024;
static constexpr int THREADS = 256;            // 8 warps -> 8 rows per block
static constexpr int WARPS = THREADS / 32;
static constexpr int VPT = 8;                  // float4 loads per thread
static constexpr int CAP = 128;                // candidate buffer per warp

__device__ __forceinline__ float4 ldg_ca_v4(const float4* p) {
    float4 v;
    asm volatile("ld.global.ca.v4.f32 {%0,%1,%2,%3}, [%4];"
                 : "=f"(v.x), "=f"(v.y), "=f"(v.z), "=f"(v.w)
                 : "l"(p));
    return v;
}

__global__ __launch_bounds__(THREADS, 5)
void sparsemax_kernel(const float* __restrict__ x, float* __restrict__ out) {
    __shared__ float cand[WARPS][CAP];

    const int lane = threadIdx.x & 31;
    const int w    = threadIdx.x >> 5;
    const int row  = blockIdx.x * WARPS + w;
    const size_t base = (size_t)row * N;

    const float4* __restrict__ xr  = reinterpret_cast<const float4*>(x + base);
    float4*       __restrict__ orw = reinterpret_cast<float4*>(out + base);

    // ---- pass 1: warp max (DRAM read; 8 independent LDG.128, front-batched) ----
    float m = -3.402823466e38f;
    #pragma unroll
    for (int i = 0; i < VPT; ++i) {
        float4 v = xr[lane + 32 * i];
        m = fmaxf(m, fmaxf(fmaxf(v.x, v.y), fmaxf(v.z, v.w)));
    }
    #pragma unroll
    for (int o = 16; o > 0; o >>= 1)
        m = fmaxf(m, __shfl_xor_sync(0xFFFFFFFFu, m, o));

    // tau in [-1, 0): support subset of {x > m - 1}
    const float thr = m - 1.0f;

    // ---- pass 2: ballot-compact candidates (L1-hit re-read) ----
    int cbase = 0;
    #pragma unroll
    for (int i = 0; i < VPT; ++i) {
        float4 v = ldg_ca_v4(&xr[lane + 32 * i]);
        const float vv[4] = { v.x, v.y, v.z, v.w };
        #pragma unroll
        for (int j = 0; j < 4; ++j) {
            bool p = vv[j] > thr;
            unsigned mask = __ballot_sync(0xFFFFFFFFu, p);
            if (p) {
                int pos = cbase + __popc(mask & ((1u << lane) - 1u));
                if (pos < CAP) cand[w][pos] = vv[j] - m;
            }
            cbase += __popc(mask);
        }
    }
    __syncwarp();
    const int c = cbase;

    // ---- pass 3: exact closed-form tau on the candidate set ----
    float tau;
    if (c <= CAP) {
        // For each candidate slot: rank r and prefix-ordered sum S over the
        // (value desc, slot asc) total order. cond = (1 + r*v > S).
        // k = max cond rank; num = sum cond*v; tau = (num - 1)/k.
        unsigned kmax = 0u;
        float num = 0.0f;
        for (int slot = lane; slot < c; slot += 32) {
            const float v = cand[w][slot];
            float S = 0.0f, r = 0.0f;
            for (int j = 0; j < c; ++j) {
                const float u = cand[w][j];
                bool ge = (u > v) || (u == v && j <= slot);
                if (ge) { S += u; r += 1.0f; }
            }
            if (1.0f + r * v > S) {
                if ((unsigned)r > kmax) kmax = (unsigned)r;
                num += v;
            }
        }
        kmax = __reduce_max_sync(0xFFFFFFFFu, kmax);
        #pragma unroll
        for (int o = 16; o > 0; o >>= 1)
            num += __shfl_xor_sync(0xFFFFFFFFu, num, o);
        tau = (num - 1.0f) / (float)kmax;
    } else {
        // ---- fallback (essentially never taken): reload-based Michelot ----
        float s = 0.0f;
        #pragma unroll
        for (int i = 0; i < VPT; ++i) {
            float4 v = ldg_ca_v4(&xr[lane + 32 * i]);
            s += ((v.x - m) + (v.y - m)) + ((v.z - m) + (v.w - m));
        }
        #pragma unroll
        for (int o = 16; o > 0; o >>= 1)
            s += __shfl_xor_sync(0xFFFFFFFFu, s, o);
        tau = (s - 1.0f) / (float)N;
        float prev_k = (float)N;
        #pragma unroll 1
        for (int it = 0; it < 64; ++it) {
            float ps = 0.0f, pk = 0.0f;
            #pragma unroll 1
            for (int i = 0; i < VPT; ++i) {
                float4 v = ldg_ca_v4(&xr[lane + 32 * i]);
                const float vv[4] = { v.x - m, v.y - m, v.z - m, v.w - m };
                #pragma unroll
                for (int j = 0; j < 4; ++j)
                    if (vv[j] > tau) { ps += vv[j]; pk += 1.0f; }
            }
            #pragma unroll
            for (int o = 16; o > 0; o >>= 1) {
                ps += __shfl_xor_sync(0xFFFFFFFFu, ps, o);
                pk += __shfl_xor_sync(0xFFFFFFFFu, pk, o);
            }
            float k = (pk > 0.0f) ? pk : 1.0f;
            float nt = (ps - 1.0f) / k;
            bool done = (nt == tau) && (k == prev_k);
            tau = nt;
            prev_k = k;
            if (done) break;
        }
    }

    // ---- pass 4: output max(x - (m + tau), 0) (L1-hit re-read) ----
    const float t2 = m + tau;
    #pragma unroll
    for (int i = 0; i < VPT; ++i) {
        float4 v = ldg_ca_v4(&xr[lane + 32 * i]);
        float4 o;
        o.x = fmaxf(v.x - t2, 0.0f);
        o.y = fmaxf(v.y - t2, 0.0f);
        o.z = fmaxf(v.z - t2, 0.0f);
        o.w = fmaxf(v.w - t2, 0.0f);
        orw[lane + 32 * i] = o;
    }
}

extern "C" void kernel_launch(void* const* d_in, const int* in_sizes, int n_in,
                              void* d_out, int out_size) {
    const float* x = (const float*)d_in[0];
    float* out = (float*)d_out;
    int rows = in_sizes[0] / N;
    sparsemax_kernel<<<rows / WARPS, THREADS>>>(x, out);
}